// round 17
// baseline (speedup 1.0000x reference)
#include <cuda_runtime.h>
#include <cuda_bf16.h>

#define MAX_NODES 50000
#define NFEAT 256
#define NHID  256
#define NOUT  128
#define MAX_EDGES 800000

// ---------------- scratch (device globals; no allocation allowed) -------------
__device__ __align__(16) float         g_s1[MAX_NODES * NHID];   // x @ w1 (fp32)
__device__ __align__(16) float         g_h [MAX_NODES * NHID];   // relu(agg) fp32
__device__ __align__(16) float         g_s2[MAX_NODES * NOUT];   // h @ w2 (fp32)
__device__ __align__(16) __nv_bfloat16 g_w1h[NHID * NFEAT];      // w1^T [N][K] hi
__device__ __align__(16) __nv_bfloat16 g_w1l[NHID * NFEAT];      // w1^T lo
__device__ __align__(16) __nv_bfloat16 g_w2h[NOUT * NHID];
__device__ __align__(16) __nv_bfloat16 g_w2l[NOUT * NHID];
__device__ int g_count [MAX_NODES + 1];
__device__ int g_row   [MAX_NODES + 1];
__device__ int g_cursor[MAX_NODES + 1];
__device__ int g_csr_src[MAX_EDGES];

// ---------------- small helpers ------------------------------------------------
__device__ __forceinline__ unsigned s2u(const void* p) {
    return (unsigned)__cvta_generic_to_shared(p);
}
__device__ __forceinline__ void ldsm_x4(unsigned* r, unsigned saddr) {
    asm volatile("ldmatrix.sync.aligned.m8n8.x4.shared.b16 {%0,%1,%2,%3}, [%4];"
                 : "=r"(r[0]), "=r"(r[1]), "=r"(r[2]), "=r"(r[3]) : "r"(saddr));
}
__device__ __forceinline__ void mma_bf16(float* c, const unsigned* a, const unsigned* b) {
    asm volatile("mma.sync.aligned.m16n8k16.row.col.f32.bf16.bf16.f32 "
                 "{%0,%1,%2,%3}, {%4,%5,%6,%7}, {%8,%9}, {%0,%1,%2,%3};"
                 : "+f"(c[0]), "+f"(c[1]), "+f"(c[2]), "+f"(c[3])
                 : "r"(a[0]), "r"(a[1]), "r"(a[2]), "r"(a[3]),
                   "r"(b[0]), "r"(b[1]));
}
__device__ __forceinline__ __nv_bfloat162 split_pair(float a, float b, __nv_bfloat162& lo) {
    __nv_bfloat16 ah = __float2bfloat16(a);
    __nv_bfloat16 bh = __float2bfloat16(b);
    __nv_bfloat16 al = __float2bfloat16(a - __bfloat162float(ah));
    __nv_bfloat16 bl = __float2bfloat16(b - __bfloat162float(bh));
    lo = __nv_bfloat162(al, bl);
    return __nv_bfloat162(ah, bh);
}

// ---------------- CSR build (by destination) ----------------------------------
__global__ void zero_count_kernel(int n) {
    int i = blockIdx.x * blockDim.x + threadIdx.x;
    if (i < n) g_count[i] = 0;
}
__global__ void hist_kernel(const int* __restrict__ dst, int ne) {
    int i = (blockIdx.x * blockDim.x + threadIdx.x) * 4;
#pragma unroll
    for (int j = 0; j < 4; j++)
        if (i + j < ne) atomicAdd(&g_count[dst[i + j]], 1);
}
__global__ void scan_kernel(int n) {
    __shared__ int s[1024];
    int t = threadIdx.x;
    int chunk = (n + 1023) >> 10;
    int beg = t * chunk;
    int end = min(beg + chunk, n);
    int sum = 0;
    for (int i = beg; i < end; i++) sum += g_count[i];
    s[t] = sum;
    __syncthreads();
    for (int off = 1; off < 1024; off <<= 1) {
        int v = (t >= off) ? s[t - off] : 0;
        __syncthreads();
        s[t] += v;
        __syncthreads();
    }
    int run = (t == 0) ? 0 : s[t - 1];
    for (int i = beg; i < end; i++) {
        g_row[i]    = run;
        g_cursor[i] = run;
        run += g_count[i];
    }
    if (t == 1023) g_row[n] = run;
}
__global__ void fill_kernel(const int* __restrict__ src, const int* __restrict__ dst, int ne) {
    int i = (blockIdx.x * blockDim.x + threadIdx.x) * 4;
#pragma unroll
    for (int j = 0; j < 4; j++) {
        if (i + j < ne) {
            int d = dst[i + j];
            int pos = atomicAdd(&g_cursor[d], 1);
            g_csr_src[pos] = src[i + j];
        }
    }
}

// ---------------- weight split: w[K][Nn] -> th/tl [Nn][K] ----------------------
__global__ void split_wt_kernel(const float* __restrict__ w,
                                __nv_bfloat16* __restrict__ th,
                                __nv_bfloat16* __restrict__ tl, int K, int Nn) {
    int idx = blockIdx.x * blockDim.x + threadIdx.x;
    if (idx >= K * Nn) return;
    int k = idx / Nn, nn = idx % Nn;
    float v = w[idx];
    __nv_bfloat16 h = __float2bfloat16(v);
    th[nn * K + k] = h;
    tl[nn * K + k] = __float2bfloat16(v - __bfloat162float(h));
}

// ---------------- tensor-core GEMM: C = A(fp32)[M,K] @ (Bh+Bl)^T ----------------
// A split into bf16 hi/lo on the fly during smem store (3-MMA reconstruction).
// BM=128 BN=64 BK=32, 256 threads, register-prefetch double buffering.
// bcol0: column offset of this launch's N-slice (column-sliced pipelining).
#define ASTR 40   // smem row stride in bf16 (80B, odd 16B-group stride -> conflict-free)

__global__ __launch_bounds__(256) void gemm_bf16x3_kernel(
    const float* __restrict__ A,
    const __nv_bfloat16* __restrict__ Bh, const __nv_bfloat16* __restrict__ Bl,
    float* __restrict__ C, int M, int N, int K, int bcol0)
{
    __shared__ __nv_bfloat16 sAh[128 * ASTR];
    __shared__ __nv_bfloat16 sAl[128 * ASTR];
    __shared__ __nv_bfloat16 sBh[64 * ASTR];
    __shared__ __nv_bfloat16 sBl[64 * ASTR];

    int tid = threadIdx.x;
    int lane = tid & 31;
    int wid = tid >> 5;
    int warp_m = wid & 3;
    int warp_n = wid >> 2;
    int brow = blockIdx.y * 128;
    int bcol = bcol0 + blockIdx.x * 64;

    float acc[2][4][4];
#pragma unroll
    for (int mi = 0; mi < 2; mi++)
#pragma unroll
        for (int j = 0; j < 4; j++)
#pragma unroll
            for (int e = 0; e < 4; e++) acc[mi][j][e] = 0.f;

    // ldmatrix per-thread addresses
    int a_row = warp_m * 32 + (lane & 15);
    int a_c8  = ((lane >> 4) & 1) * 8;
    unsigned aBaseH = s2u(sAh) + (unsigned)(a_row * ASTR + a_c8) * 2;
    unsigned aBaseL = s2u(sAl) + (unsigned)(a_row * ASTR + a_c8) * 2;
    int b_row = warp_n * 32 + (lane & 7) + ((lane >> 4) & 1) * 8;
    int b_c8  = ((lane >> 3) & 1) * 8;
    unsigned bBaseH = s2u(sBh) + (unsigned)(b_row * ASTR + b_c8) * 2;
    unsigned bBaseL = s2u(sBl) + (unsigned)(b_row * ASTR + b_c8) * 2;

    // global-load indices: A 128x32 fp32 = 1024 float4, 4 per thread
    int ra[4], ca[4];
#pragma unroll
    for (int i = 0; i < 4; i++) {
        int lin = tid + i * 256;
        ra[i] = lin >> 3;
        ca[i] = lin & 7;
    }
    int rb = tid >> 2;
    int cb = tid & 3;

    float4 pa[4];
    uint4  pbh, pbl;
    const float4 zf4 = make_float4(0.f, 0.f, 0.f, 0.f);

    // prologue: load tile k0=0 into registers
#pragma unroll
    for (int i = 0; i < 4; i++) {
        int grow = brow + ra[i];
        pa[i] = (grow < M) ? *(const float4*)(A + (size_t)grow * K + ca[i] * 4) : zf4;
    }
    pbh = *(const uint4*)(Bh + (size_t)(bcol + rb) * K + cb * 8);
    pbl = *(const uint4*)(Bl + (size_t)(bcol + rb) * K + cb * 8);

    for (int k0 = 0; k0 < K; k0 += 32) {
        // ---- store prefetched tile to smem (A split hi/lo here)
#pragma unroll
        for (int i = 0; i < 4; i++) {
            float4 v = pa[i];
            __nv_bfloat162 l01, l23;
            __nv_bfloat162 h01 = split_pair(v.x, v.y, l01);
            __nv_bfloat162 h23 = split_pair(v.z, v.w, l23);
            int o = ra[i] * ASTR + ca[i] * 4;
            *(__nv_bfloat162*)&sAh[o]     = h01;
            *(__nv_bfloat162*)&sAh[o + 2] = h23;
            *(__nv_bfloat162*)&sAl[o]     = l01;
            *(__nv_bfloat162*)&sAl[o + 2] = l23;
        }
        ((uint4*)sBh)[rb * 5 + cb] = pbh;
        ((uint4*)sBl)[rb * 5 + cb] = pbl;
        __syncthreads();

        // ---- prefetch next tile into registers (overlaps with MMA below)
        if (k0 + 32 < K) {
            int kn = k0 + 32;
#pragma unroll
            for (int i = 0; i < 4; i++) {
                int grow = brow + ra[i];
                pa[i] = (grow < M) ? *(const float4*)(A + (size_t)grow * K + kn + ca[i] * 4) : zf4;
            }
            pbh = *(const uint4*)(Bh + (size_t)(bcol + rb) * K + kn + cb * 8);
            pbl = *(const uint4*)(Bl + (size_t)(bcol + rb) * K + kn + cb * 8);
        }

        // ---- compute 32 k-values (2 MMA k-steps), 3-MMA split
#pragma unroll
        for (int ks = 0; ks < 32; ks += 16) {
            unsigned ah[2][4], al[2][4], bh[2][4], bl[2][4];
            ldsm_x4(ah[0], aBaseH + (unsigned)(ks) * 2);
            ldsm_x4(ah[1], aBaseH + (unsigned)(16 * ASTR + ks) * 2);
            ldsm_x4(al[0], aBaseL + (unsigned)(ks) * 2);
            ldsm_x4(al[1], aBaseL + (unsigned)(16 * ASTR + ks) * 2);
            ldsm_x4(bh[0], bBaseH + (unsigned)(ks) * 2);
            ldsm_x4(bh[1], bBaseH + (unsigned)(16 * ASTR + ks) * 2);
            ldsm_x4(bl[0], bBaseL + (unsigned)(ks) * 2);
            ldsm_x4(bl[1], bBaseL + (unsigned)(16 * ASTR + ks) * 2);
#pragma unroll
            for (int mi = 0; mi < 2; mi++) {
#pragma unroll
                for (int j = 0; j < 4; j++) {
                    const unsigned* bhp = &bh[j >> 1][(j & 1) * 2];
                    const unsigned* blp = &bl[j >> 1][(j & 1) * 2];
                    mma_bf16(acc[mi][j], ah[mi], bhp);
                    mma_bf16(acc[mi][j], ah[mi], blp);
                    mma_bf16(acc[mi][j], al[mi], bhp);
                }
            }
        }
        __syncthreads();
    }

    // ---- epilogue
    int r_base = brow + warp_m * 32 + (lane >> 2);
    int c_base = bcol + warp_n * 32 + (lane & 3) * 2;
#pragma unroll
    for (int mi = 0; mi < 2; mi++) {
#pragma unroll
        for (int j = 0; j < 4; j++) {
            int cc = c_base + j * 8;
            int r0 = r_base + mi * 16;
            if (r0 < M)
                *(float2*)(C + (size_t)r0 * N + cc) = make_float2(acc[mi][j][0], acc[mi][j][1]);
            int r1 = r0 + 8;
            if (r1 < M)
                *(float2*)(C + (size_t)r1 * N + cc) = make_float2(acc[mi][j][2], acc[mi][j][3]);
        }
    }
}

// ---------------- CSR gather-sum (column-sliced halves) -------------------------
// CLOG: log2(float4 lanes per node in this slice). SLOG: log2(row stride in float4).
// lane_off: first float4 lane of this slice. RELU: fuse relu before store.
template<int CLOG, int SLOG, bool RELU>
__device__ __forceinline__ void gather_body(const float4* __restrict__ sup,
                                            float4* __restrict__ out,
                                            int n, int lane_off) {
    int i = blockIdx.x * blockDim.x + threadIdx.x;
    int node = i >> CLOG;
    if (node >= n) return;
    int c = (i & ((1 << CLOG) - 1)) + lane_off;
    int beg = g_row[node];
    int end = g_row[node + 1];
    float4 acc = make_float4(0.f, 0.f, 0.f, 0.f);
    int j = beg;
    for (; j + 3 < end; j += 4) {
        int s0 = g_csr_src[j];
        int s1 = g_csr_src[j + 1];
        int s2 = g_csr_src[j + 2];
        int s3 = g_csr_src[j + 3];
        float4 v0 = sup[((size_t)s0 << SLOG) + c];
        float4 v1 = sup[((size_t)s1 << SLOG) + c];
        float4 v2 = sup[((size_t)s2 << SLOG) + c];
        float4 v3 = sup[((size_t)s3 << SLOG) + c];
        acc.x += (v0.x + v1.x) + (v2.x + v3.x);
        acc.y += (v0.y + v1.y) + (v2.y + v3.y);
        acc.z += (v0.z + v1.z) + (v2.z + v3.z);
        acc.w += (v0.w + v1.w) + (v2.w + v3.w);
    }
    for (; j < end; j++) {
        int s0 = g_csr_src[j];
        float4 v0 = sup[((size_t)s0 << SLOG) + c];
        acc.x += v0.x; acc.y += v0.y; acc.z += v0.z; acc.w += v0.w;
    }
    if (RELU) {
        acc.x = fmaxf(acc.x, 0.f); acc.y = fmaxf(acc.y, 0.f);
        acc.z = fmaxf(acc.z, 0.f); acc.w = fmaxf(acc.w, 0.f);
    }
    out[((size_t)node << SLOG) + c] = acc;
}

// layer1 half: 32 f4 lanes (128 feats), row stride 64 f4, relu fused
__global__ void gather1_half_kernel(int n, int lane_off) {
    gather_body<5, 6, true>((const float4*)g_s1, (float4*)g_h, n, lane_off);
}
// layer2 half: 16 f4 lanes (64 feats), row stride 32 f4
__global__ void gather2_half_kernel(float4* __restrict__ out, int n, int lane_off) {
    gather_body<4, 5, false>((const float4*)g_s2, out, n, lane_off);
}

// ---------------- launch --------------------------------------------------------
extern "C" void kernel_launch(void* const* d_in, const int* in_sizes, int n_in,
                              void* d_out, int out_size) {
    const float* x    = (const float*)d_in[0];
    const float* w1   = (const float*)d_in[1];
    const float* w2   = (const float*)d_in[2];
    const int*   esrc = (const int*)d_in[3];
    const int*   edst = (const int*)d_in[4];
    int n  = in_sizes[0] / NFEAT;
    int ne = in_sizes[3];

    __nv_bfloat16 *w1h, *w1l, *w2h, *w2l;
    float *s1, *s2, *h;
    cudaGetSymbolAddress((void**)&w1h, g_w1h);
    cudaGetSymbolAddress((void**)&w1l, g_w1l);
    cudaGetSymbolAddress((void**)&w2h, g_w2h);
    cudaGetSymbolAddress((void**)&w2l, g_w2l);
    cudaGetSymbolAddress((void**)&s1,  g_s1);
    cudaGetSymbolAddress((void**)&s2,  g_s2);
    cudaGetSymbolAddress((void**)&h,   g_h);

    // lazily create side stream + capture-safe events (host objects, no device mem)
    static cudaStream_t sSide = nullptr;
    static cudaEvent_t eFork = nullptr, ePrepW1 = nullptr,
                       eG1a = nullptr, eH1a = nullptr, eG2a = nullptr, eO2a = nullptr;
    if (!sSide) {
        cudaStreamCreateWithFlags(&sSide, cudaStreamNonBlocking);
        cudaEventCreateWithFlags(&eFork,   cudaEventDisableTiming);
        cudaEventCreateWithFlags(&ePrepW1, cudaEventDisableTiming);
        cudaEventCreateWithFlags(&eG1a,    cudaEventDisableTiming);
        cudaEventCreateWithFlags(&eH1a,    cudaEventDisableTiming);
        cudaEventCreateWithFlags(&eG2a,    cudaEventDisableTiming);
        cudaEventCreateWithFlags(&eO2a,    cudaEventDisableTiming);
    }

    int gy = (n + 127) / 128;

    // fork side stream from the (captured) main stream
    cudaEventRecord(eFork, 0);
    cudaStreamWaitEvent(sSide, eFork, 0);

    // side stream: w1 split (gemm1 gate), then w2 split + CSR build, then the
    // "a" column-halves of the gathers, each overlapping the "b" gemm halves.
    split_wt_kernel<<<(NFEAT * NHID + 255) / 256, 256, 0, sSide>>>(w1, w1h, w1l, NFEAT, NHID);
    cudaEventRecord(ePrepW1, sSide);
    split_wt_kernel<<<(NHID * NOUT + 255) / 256, 256, 0, sSide>>>(w2, w2h, w2l, NHID, NOUT);
    zero_count_kernel<<<(n + 255) / 256, 256, 0, sSide>>>(n);
    hist_kernel<<<(ne / 4 + 255) / 256, 256, 0, sSide>>>(edst, ne);
    scan_kernel<<<1, 1024, 0, sSide>>>(n);
    fill_kernel<<<(ne / 4 + 255) / 256, 256, 0, sSide>>>(esrc, edst, ne);

    // main: gemm1a (cols 0-127) -> gemm1b (cols 128-255)
    cudaStreamWaitEvent(0, ePrepW1, 0);
    gemm_bf16x3_kernel<<<dim3(2, gy), 256>>>(x, w1h, w1l, s1, n, NHID, NFEAT, 0);
    cudaEventRecord(eG1a, 0);
    gemm_bf16x3_kernel<<<dim3(2, gy), 256>>>(x, w1h, w1l, s1, n, NHID, NFEAT, 128);

    // side: gather1a (cols 0-127) overlaps gemm1b (needs gemm1a + CSR, both satisfied)
    cudaStreamWaitEvent(sSide, eG1a, 0);
    gather1_half_kernel<<<(n * 32 + 255) / 256, 256, 0, sSide>>>(n, 0);
    cudaEventRecord(eH1a, sSide);

    // main: gather1b (cols 128-255; needs gemm1b [program order] + CSR [via eH1a])
    cudaStreamWaitEvent(0, eH1a, 0);
    gather1_half_kernel<<<(n * 32 + 255) / 256, 256>>>(n, 32);

    // main: gemm2a (cols 0-63) -> gemm2b (cols 64-127); h fully ready
    gemm_bf16x3_kernel<<<dim3(1, gy), 256>>>(h, w2h, w2l, s2, n, NOUT, NHID, 0);
    cudaEventRecord(eG2a, 0);
    gemm_bf16x3_kernel<<<dim3(1, gy), 256>>>(h, w2h, w2l, s2, n, NOUT, NHID, 64);

    // side: gather2a (out cols 0-63) overlaps gemm2b
    cudaStreamWaitEvent(sSide, eG2a, 0);
    gather2_half_kernel<<<(n * 16 + 255) / 256, 256, 0, sSide>>>((float4*)d_out, n, 0);
    cudaEventRecord(eO2a, sSide);

    // main: gather2b (out cols 64-127); join side stream back before finishing
    cudaStreamWaitEvent(0, eO2a, 0);
    gather2_half_kernel<<<(n * 16 + 255) / 256, 256>>>((float4*)d_out, n, 16);
}